// round 8
// baseline (speedup 1.0000x reference)
#include <cuda_runtime.h>
#include <cuda_bf16.h>

#define B_ 16
#define S_ 2048
#define T_ 1024
#define E_ 256
#define D_ 256

typedef unsigned long long ull;

// Scratch (device globals — allocation-free per harness rules)
__device__ float g_dec_proj[B_ * T_ * E_];   // (B,T,E) = dec @ W_enc^T
__device__ float g_context[B_ * T_ * E_];    // (B,T,E)
__device__ int   g_len[B_];
__device__ int   g_kind;                     // 0=int32,1=uint8,2=float32,3=bf16

// ---------- packed f32x2 helpers (2x fp32 throughput on sm_103a) ----------
__device__ __forceinline__ ull pk2(float x, float y) {
    ull r; asm("mov.b64 %0,{%1,%2};" : "=l"(r) : "f"(x), "f"(y)); return r;
}
__device__ __forceinline__ float2 upk2(ull v) {
    float2 r; asm("mov.b64 {%0,%1},%2;" : "=f"(r.x), "=f"(r.y) : "l"(v)); return r;
}
__device__ __forceinline__ ull ffma2(ull a, ull b, ull c) {
    ull d; asm("fma.rn.f32x2 %0,%1,%2,%3;" : "=l"(d) : "l"(a), "l"(b), "l"(c)); return d;
}
__device__ __forceinline__ ull fmul2(ull a, ull b) {
    ull d; asm("mul.rn.f32x2 %0,%1,%2;" : "=l"(d) : "l"(a), "l"(b)); return d;
}

// ---------- mask dtype detection ----------
// Scans only the first 8192 words (32KB) — in-bounds under every candidate dtype.
// Prefix-mask structure guarantees distinguishing word patterns appear.
__global__ void k_detect(const unsigned int* __restrict__ m) {
    __shared__ int fl[3];
    if (threadIdx.x < 3) fl[threadIdx.x] = 0;
    __syncthreads();
    for (int i = threadIdx.x; i < 8192; i += 256) {
        unsigned v = m[i];
        if (v == 0x3F800000u) fl[0] = 1;                                        // float32 1.0
        else if (v == 0x3F803F80u || v == 0x00003F80u) fl[1] = 1;               // bf16 1.0 pair
        else if (v == 0x01010101u || v == 0x00010101u || v == 0x00000101u) fl[2] = 1; // packed bytes
    }
    __syncthreads();
    if (threadIdx.x == 0)
        g_kind = fl[0] ? 2 : (fl[1] ? 3 : (fl[2] ? 1 : 0));
}

// ---------- per-batch valid length (mask is a prefix mask) ----------
__global__ void k_len(const void* __restrict__ m) {
    int b = blockIdx.x;
    int kind = g_kind;
    int c = 0;
    for (int s = threadIdx.x; s < S_; s += 256) {
        int v;
        if (kind == 0)      v = ((const int*)m)[b * S_ + s] != 0;
        else if (kind == 1) v = ((const unsigned char*)m)[b * S_ + s] != 0;
        else if (kind == 2) v = ((const float*)m)[b * S_ + s] != 0.0f;
        else                v = ((const unsigned short*)m)[b * S_ + s] != 0;
        c += v;
    }
    __shared__ int red[256];
    red[threadIdx.x] = c;
    __syncthreads();
    for (int st = 128; st > 0; st >>= 1) {
        if (threadIdx.x < st) red[threadIdx.x] += red[threadIdx.x + st];
        __syncthreads();
    }
    if (threadIdx.x == 0) g_len[b] = red[0];
}

// ---------- K1: dec_proj[m,e] = sum_d dec[m,d] * W_enc[e,d]  (NT GEMM) ----------
__global__ __launch_bounds__(256) void k_decproj(const float* __restrict__ A,
                                                 const float* __restrict__ Bw) {
    __shared__ float As[32][64];   // [k][m] transposed
    __shared__ float Bs[32][64];   // [k][n] transposed
    const int K = D_;
    int m0 = blockIdx.y * 64, n0 = blockIdx.x * 64;
    int tid = threadIdx.x;
    int lr = tid & 63, lk = (tid >> 6) * 8;
    int ty = tid >> 4, tx = tid & 15;
    ull acc[4][2];
#pragma unroll
    for (int i = 0; i < 4; i++) { acc[i][0] = 0ull; acc[i][1] = 0ull; }
    const float* arow = A  + (size_t)(m0 + lr) * K;
    const float* brow = Bw + (size_t)(n0 + lr) * K;
    for (int k0 = 0; k0 < K; k0 += 32) {
        float4 a0 = *(const float4*)(arow + k0 + lk);
        float4 a1 = *(const float4*)(arow + k0 + lk + 4);
        float4 b0 = *(const float4*)(brow + k0 + lk);
        float4 b1 = *(const float4*)(brow + k0 + lk + 4);
        As[lk + 0][lr] = a0.x; As[lk + 1][lr] = a0.y; As[lk + 2][lr] = a0.z; As[lk + 3][lr] = a0.w;
        As[lk + 4][lr] = a1.x; As[lk + 5][lr] = a1.y; As[lk + 6][lr] = a1.z; As[lk + 7][lr] = a1.w;
        Bs[lk + 0][lr] = b0.x; Bs[lk + 1][lr] = b0.y; Bs[lk + 2][lr] = b0.z; Bs[lk + 3][lr] = b0.w;
        Bs[lk + 4][lr] = b1.x; Bs[lk + 5][lr] = b1.y; Bs[lk + 6][lr] = b1.z; Bs[lk + 7][lr] = b1.w;
        __syncthreads();
#pragma unroll
        for (int k = 0; k < 32; k++) {
            float4 av = *(const float4*)&As[k][4 * ty];
            float4 bv = *(const float4*)&Bs[k][4 * tx];
            ull b01 = pk2(bv.x, bv.y), b23 = pk2(bv.z, bv.w);
            ull aa;
            aa = pk2(av.x, av.x); acc[0][0] = ffma2(aa, b01, acc[0][0]); acc[0][1] = ffma2(aa, b23, acc[0][1]);
            aa = pk2(av.y, av.y); acc[1][0] = ffma2(aa, b01, acc[1][0]); acc[1][1] = ffma2(aa, b23, acc[1][1]);
            aa = pk2(av.z, av.z); acc[2][0] = ffma2(aa, b01, acc[2][0]); acc[2][1] = ffma2(aa, b23, acc[2][1]);
            aa = pk2(av.w, av.w); acc[3][0] = ffma2(aa, b01, acc[3][0]); acc[3][1] = ffma2(aa, b23, acc[3][1]);
        }
        __syncthreads();
    }
    float* crow = g_dec_proj + (size_t)(m0 + 4 * ty) * E_ + n0 + 4 * tx;
#pragma unroll
    for (int i = 0; i < 4; i++) {
        float2 c0 = upk2(acc[i][0]), c1 = upk2(acc[i][1]);
        *(float4*)(crow + (size_t)i * E_) = make_float4(c0.x, c0.y, c1.x, c1.y);
    }
}

// ---------- K2: fused flash attention (K == V == enc_states) ----------
// Grid: (T/64, B). One CTA = 64 dec rows. Loops only over valid-prefix chunks.
#define SMEM_FLOATS (256 * 64 + 256 * 68 + 64 * 256 + 64 * 68)

__global__ __launch_bounds__(256, 1) void k_attn(const float* __restrict__ enc,
                                                 float* __restrict__ ctxout) {
    extern __shared__ float sm[];
    float* Qs = sm;                 // [256][64]  (k-major transposed dec_proj tile)
    float* Es = Qs + 256 * 64;      // [256][68]  (k-major transposed enc chunk, padded)
    float* Vs = Es + 256 * 68;      // [64][256]  (natural enc chunk, XOR-swizzled)
    float* Ps = Vs + 64 * 256;      // [64][68]   (softmax weights)

    int b = blockIdx.y;
    int t0 = blockIdx.x * 64;
    int tid = threadIdx.x, ty = tid >> 4, tx = tid & 15;
    int lr = tid & 63, le8 = (tid >> 6) * 8;

    // Load Q tile transposed: Qs[e][t_local]
    const float* qrow = g_dec_proj + ((size_t)b * T_ + t0 + lr) * E_;
#pragma unroll
    for (int e = le8; e < 256; e += 32) {
        float4 v0 = *(const float4*)(qrow + e);
        float4 v1 = *(const float4*)(qrow + e + 4);
        Qs[(e + 0) * 64 + lr] = v0.x; Qs[(e + 1) * 64 + lr] = v0.y;
        Qs[(e + 2) * 64 + lr] = v0.z; Qs[(e + 3) * 64 + lr] = v0.w;
        Qs[(e + 4) * 64 + lr] = v1.x; Qs[(e + 5) * 64 + lr] = v1.y;
        Qs[(e + 6) * 64 + lr] = v1.z; Qs[(e + 7) * 64 + lr] = v1.w;
    }

    int len = g_len[b];
    int nch = (len + 63) >> 6;

    float mr[4], lrw[4];
    ull acc[4][8];
#pragma unroll
    for (int i = 0; i < 4; i++) {
        mr[i] = __int_as_float(0xff800000); lrw[i] = 0.0f;
#pragma unroll
        for (int j = 0; j < 8; j++) acc[i][j] = 0ull;
    }

    int vsw = (lr & 7) * 4;  // Vs write swizzle (low-bank XOR, keeps 16B alignment)

    for (int sc = 0; sc < nch; sc++) {
        int s0 = sc << 6;
        const float* erow = enc + ((size_t)b * S_ + s0 + lr) * E_;
#pragma unroll
        for (int e = le8; e < 256; e += 32) {
            float4 v0 = *(const float4*)(erow + e);
            float4 v1 = *(const float4*)(erow + e + 4);
            *(float4*)&Vs[lr * 256 + ((e) ^ vsw)]     = v0;
            *(float4*)&Vs[lr * 256 + ((e + 4) ^ vsw)] = v1;
            Es[(e + 0) * 68 + lr] = v0.x; Es[(e + 1) * 68 + lr] = v0.y;
            Es[(e + 2) * 68 + lr] = v0.z; Es[(e + 3) * 68 + lr] = v0.w;
            Es[(e + 4) * 68 + lr] = v1.x; Es[(e + 5) * 68 + lr] = v1.y;
            Es[(e + 6) * 68 + lr] = v1.z; Es[(e + 7) * 68 + lr] = v1.w;
        }
        __syncthreads();

        // -------- Phase A: scores tile (64x64) = Q @ enc^T --------
        ull s2[4][2];
#pragma unroll
        for (int i = 0; i < 4; i++) { s2[i][0] = 0ull; s2[i][1] = 0ull; }
#pragma unroll 8
        for (int k = 0; k < 256; k++) {
            float4 q  = *(const float4*)&Qs[k * 64 + 4 * ty];
            float4 e4 = *(const float4*)&Es[k * 68 + 4 * tx];
            ull b01 = pk2(e4.x, e4.y), b23 = pk2(e4.z, e4.w);
            ull aa;
            aa = pk2(q.x, q.x); s2[0][0] = ffma2(aa, b01, s2[0][0]); s2[0][1] = ffma2(aa, b23, s2[0][1]);
            aa = pk2(q.y, q.y); s2[1][0] = ffma2(aa, b01, s2[1][0]); s2[1][1] = ffma2(aa, b23, s2[1][1]);
            aa = pk2(q.z, q.z); s2[2][0] = ffma2(aa, b01, s2[2][0]); s2[2][1] = ffma2(aa, b23, s2[2][1]);
            aa = pk2(q.w, q.w); s2[3][0] = ffma2(aa, b01, s2[3][0]); s2[3][1] = ffma2(aa, b23, s2[3][1]);
        }

        // -------- online softmax update --------
        int rem = len - s0;
#pragma unroll
        for (int i = 0; i < 4; i++) {
            float2 c0 = upk2(s2[i][0]), c1 = upk2(s2[i][1]);
            float sv0 = c0.x, sv1 = c0.y, sv2 = c1.x, sv3 = c1.y;
            if (rem < 64) {
                const float NINF = __int_as_float(0xff800000);
                if (4 * tx + 0 >= rem) sv0 = NINF;
                if (4 * tx + 1 >= rem) sv1 = NINF;
                if (4 * tx + 2 >= rem) sv2 = NINF;
                if (4 * tx + 3 >= rem) sv3 = NINF;
            }
            float cm = fmaxf(fmaxf(sv0, sv1), fmaxf(sv2, sv3));
#pragma unroll
            for (int off = 1; off < 16; off <<= 1)
                cm = fmaxf(cm, __shfl_xor_sync(0xffffffffu, cm, off));
            float nm = fmaxf(mr[i], cm);
            float scale = __expf(mr[i] - nm);
            mr[i] = nm;
            float p0 = __expf(sv0 - nm), p1 = __expf(sv1 - nm);
            float p2 = __expf(sv2 - nm), p3 = __expf(sv3 - nm);
            float rs = (p0 + p1) + (p2 + p3);
#pragma unroll
            for (int off = 1; off < 16; off <<= 1)
                rs += __shfl_xor_sync(0xffffffffu, rs, off);
            lrw[i] = lrw[i] * scale + rs;
            ull sc2 = pk2(scale, scale);
#pragma unroll
            for (int j = 0; j < 8; j++) acc[i][j] = fmul2(sc2, acc[i][j]);
            *(float4*)&Ps[(4 * ty + i) * 68 + 4 * tx] = make_float4(p0, p1, p2, p3);
        }
        __syncthreads();

        // -------- Phase B: context += P @ V --------
#pragma unroll 1
        for (int s4 = 0; s4 < 64; s4 += 4) {
            float4 pr0 = *(const float4*)&Ps[(4 * ty + 0) * 68 + s4];
            float4 pr1 = *(const float4*)&Ps[(4 * ty + 1) * 68 + s4];
            float4 pr2 = *(const float4*)&Ps[(4 * ty + 2) * 68 + s4];
            float4 pr3 = *(const float4*)&Ps[(4 * ty + 3) * 68 + s4];
            float pm0[4] = {pr0.x, pr0.y, pr0.z, pr0.w};
            float pm1[4] = {pr1.x, pr1.y, pr1.z, pr1.w};
            float pm2[4] = {pr2.x, pr2.y, pr2.z, pr2.w};
            float pm3[4] = {pr3.x, pr3.y, pr3.z, pr3.w};
#pragma unroll
            for (int u = 0; u < 4; u++) {
                const float* vb = &Vs[(s4 + u) * 256];
                int co = (2 * tx) ^ (((s4 + u) & 7) * 4);
                ull pp0 = pk2(pm0[u], pm0[u]);
                ull pp1 = pk2(pm1[u], pm1[u]);
                ull pp2 = pk2(pm2[u], pm2[u]);
                ull pp3 = pk2(pm3[u], pm3[u]);
#pragma unroll
                for (int jj = 0; jj < 8; jj++) {
                    ull v2 = *(const ull*)(vb + co + 32 * jj);
                    acc[0][jj] = ffma2(pp0, v2, acc[0][jj]);
                    acc[1][jj] = ffma2(pp1, v2, acc[1][jj]);
                    acc[2][jj] = ffma2(pp2, v2, acc[2][jj]);
                    acc[3][jj] = ffma2(pp3, v2, acc[3][jj]);
                }
            }
        }
        __syncthreads();
    }

    // -------- epilogue: normalize and write context --------
#pragma unroll
    for (int i = 0; i < 4; i++) {
        float inv = 1.0f / lrw[i];
        float* orow = ctxout + ((size_t)b * T_ + t0 + 4 * ty + i) * E_ + 2 * tx;
#pragma unroll
        for (int jj = 0; jj < 8; jj++) {
            float2 c = upk2(acc[i][jj]);
            *(float2*)(orow + 32 * jj) = make_float2(c.x * inv, c.y * inv);
        }
    }
}

// ---------- K3: out = tanh([context, dec] @ W_fin)  (NN GEMM, K=512) ----------
__global__ __launch_bounds__(256) void k_final(const float* __restrict__ dec,
                                               const float* __restrict__ W,
                                               float* __restrict__ out) {
    __shared__ float As[32][64];   // [k][m] transposed
    __shared__ float Bs[32][68];   // [k][n] natural, padded
    int m0 = blockIdx.y * 64, n0 = blockIdx.x * 64;
    int tid = threadIdx.x;
    int lr = tid & 63, lk = (tid >> 6) * 8;
    int ty = tid >> 4, tx = tid & 15;
    int bkk = tid >> 4, bnn = (tid & 15) * 4;
    ull acc[4][2];
#pragma unroll
    for (int i = 0; i < 4; i++) { acc[i][0] = 0ull; acc[i][1] = 0ull; }

    for (int k0 = 0; k0 < 512; k0 += 32) {
        const float* arow = (k0 < 256)
            ? (g_context + (size_t)(m0 + lr) * E_ + k0)
            : (dec + (size_t)(m0 + lr) * D_ + (k0 - 256));
        float4 a0 = *(const float4*)(arow + lk);
        float4 a1 = *(const float4*)(arow + lk + 4);
        float4 w0 = *(const float4*)&W[(size_t)(k0 + bkk) * D_ + n0 + bnn];
        float4 w1 = *(const float4*)&W[(size_t)(k0 + bkk + 16) * D_ + n0 + bnn];
        As[lk + 0][lr] = a0.x; As[lk + 1][lr] = a0.y; As[lk + 2][lr] = a0.z; As[lk + 3][lr] = a0.w;
        As[lk + 4][lr] = a1.x; As[lk + 5][lr] = a1.y; As[lk + 6][lr] = a1.z; As[lk + 7][lr] = a1.w;
        *(float4*)&Bs[bkk][bnn]      = w0;
        *(float4*)&Bs[bkk + 16][bnn] = w1;
        __syncthreads();
#pragma unroll
        for (int k = 0; k < 32; k++) {
            float4 av = *(const float4*)&As[k][4 * ty];
            float4 bv = *(const float4*)&Bs[k][4 * tx];
            ull b01 = pk2(bv.x, bv.y), b23 = pk2(bv.z, bv.w);
            ull aa;
            aa = pk2(av.x, av.x); acc[0][0] = ffma2(aa, b01, acc[0][0]); acc[0][1] = ffma2(aa, b23, acc[0][1]);
            aa = pk2(av.y, av.y); acc[1][0] = ffma2(aa, b01, acc[1][0]); acc[1][1] = ffma2(aa, b23, acc[1][1]);
            aa = pk2(av.z, av.z); acc[2][0] = ffma2(aa, b01, acc[2][0]); acc[2][1] = ffma2(aa, b23, acc[2][1]);
            aa = pk2(av.w, av.w); acc[3][0] = ffma2(aa, b01, acc[3][0]); acc[3][1] = ffma2(aa, b23, acc[3][1]);
        }
        __syncthreads();
    }
    float* crow = out + (size_t)(m0 + 4 * ty) * D_ + n0 + 4 * tx;
#pragma unroll
    for (int i = 0; i < 4; i++) {
        float2 c0 = upk2(acc[i][0]), c1 = upk2(acc[i][1]);
        *(float4*)(crow + (size_t)i * D_) =
            make_float4(tanhf(c0.x), tanhf(c0.y), tanhf(c1.x), tanhf(c1.y));
    }
}

// ---------- launch ----------
extern "C" void kernel_launch(void* const* d_in, const int* in_sizes, int n_in,
                              void* d_out, int out_size) {
    const float* enc  = (const float*)d_in[0];   // (B,S,E)
    const float* dec  = (const float*)d_in[1];   // (B,T,D)
    const void*  mask = d_in[2];                 // (B,S) bool-ish
    const float* Wenc = (const float*)d_in[3];   // (E,D)
    const float* Wfin = (const float*)d_in[4];   // (E+D,D)
    float* out = (float*)d_out;                  // (B,T,D)

    const size_t smem = (size_t)SMEM_FLOATS * sizeof(float);  // 218112 B
    cudaFuncSetAttribute(k_attn, cudaFuncAttributeMaxDynamicSharedMemorySize, (int)smem);

    k_detect<<<1, 256>>>((const unsigned int*)mask);
    k_len<<<B_, 256>>>(mask);

    // context pointer for k_attn output: device global, retrieved via kernel arg trick:
    // k_attn writes g_context directly? It takes ctxout param — pass via symbol-less route:
    k_decproj<<<dim3(E_ / 64, (B_ * T_) / 64), 256>>>(dec, Wenc);

    // We cannot take the address of a __device__ array on the host without
    // cudaGetSymbolAddress (allowed — not an allocation), do it once per call.
    void* ctxptr = nullptr;
    cudaGetSymbolAddress(&ctxptr, g_context);
    k_attn<<<dim3(T_ / 64, B_), 256, smem>>>(enc, (float*)ctxptr);

    k_final<<<dim3(D_ / 64, (B_ * T_) / 64), 256>>>(dec, Wfin, out);
}

// round 9
// speedup vs baseline: 1.0004x; 1.0004x over previous
#include <cuda_runtime.h>
#include <cuda_bf16.h>

#define B_ 16
#define S_ 2048
#define T_ 1024
#define E_ 256
#define D_ 256

typedef unsigned long long ull;

// Scratch (device globals — allocation-free per harness rules)
__device__ float g_dec_proj[B_ * T_ * E_];   // (B,T,E) = dec @ W_enc^T
__device__ float g_context[B_ * T_ * E_];    // (B,T,E)
__device__ int   g_len[B_];
__device__ int   g_kind;                     // 0=int32,1=uint8,2=float32,3=bf16

// ---------- packed f32x2 helpers (2x fp32 throughput on sm_103a) ----------
__device__ __forceinline__ ull pk2(float x, float y) {
    ull r; asm("mov.b64 %0,{%1,%2};" : "=l"(r) : "f"(x), "f"(y)); return r;
}
__device__ __forceinline__ float2 upk2(ull v) {
    float2 r; asm("mov.b64 {%0,%1},%2;" : "=f"(r.x), "=f"(r.y) : "l"(v)); return r;
}
__device__ __forceinline__ ull ffma2(ull a, ull b, ull c) {
    ull d; asm("fma.rn.f32x2 %0,%1,%2,%3;" : "=l"(d) : "l"(a), "l"(b), "l"(c)); return d;
}
__device__ __forceinline__ ull fmul2(ull a, ull b) {
    ull d; asm("mul.rn.f32x2 %0,%1,%2;" : "=l"(d) : "l"(a), "l"(b)); return d;
}

// ---------- mask dtype detection ----------
// Scans only the first 8192 words (32KB) — in-bounds under every candidate dtype.
// Prefix-mask structure guarantees distinguishing word patterns appear.
__global__ void k_detect(const unsigned int* __restrict__ m) {
    __shared__ int fl[3];
    if (threadIdx.x < 3) fl[threadIdx.x] = 0;
    __syncthreads();
    for (int i = threadIdx.x; i < 8192; i += 256) {
        unsigned v = m[i];
        if (v == 0x3F800000u) fl[0] = 1;                                        // float32 1.0
        else if (v == 0x3F803F80u || v == 0x00003F80u) fl[1] = 1;               // bf16 1.0 pair
        else if (v == 0x01010101u || v == 0x00010101u || v == 0x00000101u) fl[2] = 1; // packed bytes
    }
    __syncthreads();
    if (threadIdx.x == 0)
        g_kind = fl[0] ? 2 : (fl[1] ? 3 : (fl[2] ? 1 : 0));
}

// ---------- per-batch valid length (mask is a prefix mask) ----------
__global__ void k_len(const void* __restrict__ m) {
    int b = blockIdx.x;
    int kind = g_kind;
    int c = 0;
    for (int s = threadIdx.x; s < S_; s += 256) {
        int v;
        if (kind == 0)      v = ((const int*)m)[b * S_ + s] != 0;
        else if (kind == 1) v = ((const unsigned char*)m)[b * S_ + s] != 0;
        else if (kind == 2) v = ((const float*)m)[b * S_ + s] != 0.0f;
        else                v = ((const unsigned short*)m)[b * S_ + s] != 0;
        c += v;
    }
    __shared__ int red[256];
    red[threadIdx.x] = c;
    __syncthreads();
    for (int st = 128; st > 0; st >>= 1) {
        if (threadIdx.x < st) red[threadIdx.x] += red[threadIdx.x + st];
        __syncthreads();
    }
    if (threadIdx.x == 0) g_len[b] = red[0];
}

// ---------- K1: dec_proj[m,e] = sum_d dec[m,d] * W_enc[e,d]  (NT GEMM) ----------
__global__ __launch_bounds__(256) void k_decproj(const float* __restrict__ A,
                                                 const float* __restrict__ Bw) {
    __shared__ float As[32][64];   // [k][m] transposed
    __shared__ float Bs[32][64];   // [k][n] transposed
    const int K = D_;
    int m0 = blockIdx.y * 64, n0 = blockIdx.x * 64;
    int tid = threadIdx.x;
    int lr = tid & 63, lk = (tid >> 6) * 8;
    int ty = tid >> 4, tx = tid & 15;
    ull acc[4][2];
#pragma unroll
    for (int i = 0; i < 4; i++) { acc[i][0] = 0ull; acc[i][1] = 0ull; }
    const float* arow = A  + (size_t)(m0 + lr) * K;
    const float* brow = Bw + (size_t)(n0 + lr) * K;
    for (int k0 = 0; k0 < K; k0 += 32) {
        float4 a0 = *(const float4*)(arow + k0 + lk);
        float4 a1 = *(const float4*)(arow + k0 + lk + 4);
        float4 b0 = *(const float4*)(brow + k0 + lk);
        float4 b1 = *(const float4*)(brow + k0 + lk + 4);
        As[lk + 0][lr] = a0.x; As[lk + 1][lr] = a0.y; As[lk + 2][lr] = a0.z; As[lk + 3][lr] = a0.w;
        As[lk + 4][lr] = a1.x; As[lk + 5][lr] = a1.y; As[lk + 6][lr] = a1.z; As[lk + 7][lr] = a1.w;
        Bs[lk + 0][lr] = b0.x; Bs[lk + 1][lr] = b0.y; Bs[lk + 2][lr] = b0.z; Bs[lk + 3][lr] = b0.w;
        Bs[lk + 4][lr] = b1.x; Bs[lk + 5][lr] = b1.y; Bs[lk + 6][lr] = b1.z; Bs[lk + 7][lr] = b1.w;
        __syncthreads();
#pragma unroll
        for (int k = 0; k < 32; k++) {
            float4 av = *(const float4*)&As[k][4 * ty];
            float4 bv = *(const float4*)&Bs[k][4 * tx];
            ull b01 = pk2(bv.x, bv.y), b23 = pk2(bv.z, bv.w);
            ull aa;
            aa = pk2(av.x, av.x); acc[0][0] = ffma2(aa, b01, acc[0][0]); acc[0][1] = ffma2(aa, b23, acc[0][1]);
            aa = pk2(av.y, av.y); acc[1][0] = ffma2(aa, b01, acc[1][0]); acc[1][1] = ffma2(aa, b23, acc[1][1]);
            aa = pk2(av.z, av.z); acc[2][0] = ffma2(aa, b01, acc[2][0]); acc[2][1] = ffma2(aa, b23, acc[2][1]);
            aa = pk2(av.w, av.w); acc[3][0] = ffma2(aa, b01, acc[3][0]); acc[3][1] = ffma2(aa, b23, acc[3][1]);
        }
        __syncthreads();
    }
    float* crow = g_dec_proj + (size_t)(m0 + 4 * ty) * E_ + n0 + 4 * tx;
#pragma unroll
    for (int i = 0; i < 4; i++) {
        float2 c0 = upk2(acc[i][0]), c1 = upk2(acc[i][1]);
        *(float4*)(crow + (size_t)i * E_) = make_float4(c0.x, c0.y, c1.x, c1.y);
    }
}

// ---------- K2: fused flash attention (K == V == enc_states) ----------
// Grid: (T/64, B). One CTA = 64 dec rows. Loops only over valid-prefix chunks.
#define SMEM_FLOATS (256 * 64 + 256 * 68 + 64 * 256 + 64 * 68)

__global__ __launch_bounds__(256, 1) void k_attn(const float* __restrict__ enc,
                                                 float* __restrict__ ctxout) {
    extern __shared__ float sm[];
    float* Qs = sm;                 // [256][64]  (k-major transposed dec_proj tile)
    float* Es = Qs + 256 * 64;      // [256][68]  (k-major transposed enc chunk, padded)
    float* Vs = Es + 256 * 68;      // [64][256]  (natural enc chunk, XOR-swizzled)
    float* Ps = Vs + 64 * 256;      // [64][68]   (softmax weights)

    int b = blockIdx.y;
    int t0 = blockIdx.x * 64;
    int tid = threadIdx.x, ty = tid >> 4, tx = tid & 15;
    int lr = tid & 63, le8 = (tid >> 6) * 8;

    // Load Q tile transposed: Qs[e][t_local]
    const float* qrow = g_dec_proj + ((size_t)b * T_ + t0 + lr) * E_;
#pragma unroll
    for (int e = le8; e < 256; e += 32) {
        float4 v0 = *(const float4*)(qrow + e);
        float4 v1 = *(const float4*)(qrow + e + 4);
        Qs[(e + 0) * 64 + lr] = v0.x; Qs[(e + 1) * 64 + lr] = v0.y;
        Qs[(e + 2) * 64 + lr] = v0.z; Qs[(e + 3) * 64 + lr] = v0.w;
        Qs[(e + 4) * 64 + lr] = v1.x; Qs[(e + 5) * 64 + lr] = v1.y;
        Qs[(e + 6) * 64 + lr] = v1.z; Qs[(e + 7) * 64 + lr] = v1.w;
    }

    int len = g_len[b];
    int nch = (len + 63) >> 6;

    float mr[4], lrw[4];
    ull acc[4][8];
#pragma unroll
    for (int i = 0; i < 4; i++) {
        mr[i] = __int_as_float(0xff800000); lrw[i] = 0.0f;
#pragma unroll
        for (int j = 0; j < 8; j++) acc[i][j] = 0ull;
    }

    int vsw = (lr & 7) * 4;  // Vs write swizzle (low-bank XOR, keeps 16B alignment)

    for (int sc = 0; sc < nch; sc++) {
        int s0 = sc << 6;
        const float* erow = enc + ((size_t)b * S_ + s0 + lr) * E_;
#pragma unroll
        for (int e = le8; e < 256; e += 32) {
            float4 v0 = *(const float4*)(erow + e);
            float4 v1 = *(const float4*)(erow + e + 4);
            *(float4*)&Vs[lr * 256 + ((e) ^ vsw)]     = v0;
            *(float4*)&Vs[lr * 256 + ((e + 4) ^ vsw)] = v1;
            Es[(e + 0) * 68 + lr] = v0.x; Es[(e + 1) * 68 + lr] = v0.y;
            Es[(e + 2) * 68 + lr] = v0.z; Es[(e + 3) * 68 + lr] = v0.w;
            Es[(e + 4) * 68 + lr] = v1.x; Es[(e + 5) * 68 + lr] = v1.y;
            Es[(e + 6) * 68 + lr] = v1.z; Es[(e + 7) * 68 + lr] = v1.w;
        }
        __syncthreads();

        // -------- Phase A: scores tile (64x64) = Q @ enc^T --------
        ull s2[4][2];
#pragma unroll
        for (int i = 0; i < 4; i++) { s2[i][0] = 0ull; s2[i][1] = 0ull; }
#pragma unroll 8
        for (int k = 0; k < 256; k++) {
            float4 q  = *(const float4*)&Qs[k * 64 + 4 * ty];
            float4 e4 = *(const float4*)&Es[k * 68 + 4 * tx];
            ull b01 = pk2(e4.x, e4.y), b23 = pk2(e4.z, e4.w);
            ull aa;
            aa = pk2(q.x, q.x); s2[0][0] = ffma2(aa, b01, s2[0][0]); s2[0][1] = ffma2(aa, b23, s2[0][1]);
            aa = pk2(q.y, q.y); s2[1][0] = ffma2(aa, b01, s2[1][0]); s2[1][1] = ffma2(aa, b23, s2[1][1]);
            aa = pk2(q.z, q.z); s2[2][0] = ffma2(aa, b01, s2[2][0]); s2[2][1] = ffma2(aa, b23, s2[2][1]);
            aa = pk2(q.w, q.w); s2[3][0] = ffma2(aa, b01, s2[3][0]); s2[3][1] = ffma2(aa, b23, s2[3][1]);
        }

        // -------- online softmax update --------
        int rem = len - s0;
#pragma unroll
        for (int i = 0; i < 4; i++) {
            float2 c0 = upk2(s2[i][0]), c1 = upk2(s2[i][1]);
            float sv0 = c0.x, sv1 = c0.y, sv2 = c1.x, sv3 = c1.y;
            if (rem < 64) {
                const float NINF = __int_as_float(0xff800000);
                if (4 * tx + 0 >= rem) sv0 = NINF;
                if (4 * tx + 1 >= rem) sv1 = NINF;
                if (4 * tx + 2 >= rem) sv2 = NINF;
                if (4 * tx + 3 >= rem) sv3 = NINF;
            }
            float cm = fmaxf(fmaxf(sv0, sv1), fmaxf(sv2, sv3));
#pragma unroll
            for (int off = 1; off < 16; off <<= 1)
                cm = fmaxf(cm, __shfl_xor_sync(0xffffffffu, cm, off));
            float nm = fmaxf(mr[i], cm);
            float scale = __expf(mr[i] - nm);
            mr[i] = nm;
            float p0 = __expf(sv0 - nm), p1 = __expf(sv1 - nm);
            float p2 = __expf(sv2 - nm), p3 = __expf(sv3 - nm);
            float rs = (p0 + p1) + (p2 + p3);
#pragma unroll
            for (int off = 1; off < 16; off <<= 1)
                rs += __shfl_xor_sync(0xffffffffu, rs, off);
            lrw[i] = lrw[i] * scale + rs;
            ull sc2 = pk2(scale, scale);
#pragma unroll
            for (int j = 0; j < 8; j++) acc[i][j] = fmul2(sc2, acc[i][j]);
            *(float4*)&Ps[(4 * ty + i) * 68 + 4 * tx] = make_float4(p0, p1, p2, p3);
        }
        __syncthreads();

        // -------- Phase B: context += P @ V --------
#pragma unroll 1
        for (int s4 = 0; s4 < 64; s4 += 4) {
            float4 pr0 = *(const float4*)&Ps[(4 * ty + 0) * 68 + s4];
            float4 pr1 = *(const float4*)&Ps[(4 * ty + 1) * 68 + s4];
            float4 pr2 = *(const float4*)&Ps[(4 * ty + 2) * 68 + s4];
            float4 pr3 = *(const float4*)&Ps[(4 * ty + 3) * 68 + s4];
            float pm0[4] = {pr0.x, pr0.y, pr0.z, pr0.w};
            float pm1[4] = {pr1.x, pr1.y, pr1.z, pr1.w};
            float pm2[4] = {pr2.x, pr2.y, pr2.z, pr2.w};
            float pm3[4] = {pr3.x, pr3.y, pr3.z, pr3.w};
#pragma unroll
            for (int u = 0; u < 4; u++) {
                const float* vb = &Vs[(s4 + u) * 256];
                int co = (2 * tx) ^ (((s4 + u) & 7) * 4);
                ull pp0 = pk2(pm0[u], pm0[u]);
                ull pp1 = pk2(pm1[u], pm1[u]);
                ull pp2 = pk2(pm2[u], pm2[u]);
                ull pp3 = pk2(pm3[u], pm3[u]);
#pragma unroll
                for (int jj = 0; jj < 8; jj++) {
                    ull v2 = *(const ull*)(vb + co + 32 * jj);
                    acc[0][jj] = ffma2(pp0, v2, acc[0][jj]);
                    acc[1][jj] = ffma2(pp1, v2, acc[1][jj]);
                    acc[2][jj] = ffma2(pp2, v2, acc[2][jj]);
                    acc[3][jj] = ffma2(pp3, v2, acc[3][jj]);
                }
            }
        }
        __syncthreads();
    }

    // -------- epilogue: normalize and write context --------
#pragma unroll
    for (int i = 0; i < 4; i++) {
        float inv = 1.0f / lrw[i];
        float* orow = ctxout + ((size_t)b * T_ + t0 + 4 * ty + i) * E_ + 2 * tx;
#pragma unroll
        for (int jj = 0; jj < 8; jj++) {
            float2 c = upk2(acc[i][jj]);
            *(float2*)(orow + 32 * jj) = make_float2(c.x * inv, c.y * inv);
        }
    }
}

// ---------- K3: out = tanh([context, dec] @ W_fin)  (NN GEMM, K=512) ----------
__global__ __launch_bounds__(256) void k_final(const float* __restrict__ dec,
                                               const float* __restrict__ W,
                                               float* __restrict__ out) {
    __shared__ float As[32][64];   // [k][m] transposed
    __shared__ float Bs[32][68];   // [k][n] natural, padded
    int m0 = blockIdx.y * 64, n0 = blockIdx.x * 64;
    int tid = threadIdx.x;
    int lr = tid & 63, lk = (tid >> 6) * 8;
    int ty = tid >> 4, tx = tid & 15;
    int bkk = tid >> 4, bnn = (tid & 15) * 4;
    ull acc[4][2];
#pragma unroll
    for (int i = 0; i < 4; i++) { acc[i][0] = 0ull; acc[i][1] = 0ull; }

    for (int k0 = 0; k0 < 512; k0 += 32) {
        const float* arow = (k0 < 256)
            ? (g_context + (size_t)(m0 + lr) * E_ + k0)
            : (dec + (size_t)(m0 + lr) * D_ + (k0 - 256));
        float4 a0 = *(const float4*)(arow + lk);
        float4 a1 = *(const float4*)(arow + lk + 4);
        float4 w0 = *(const float4*)&W[(size_t)(k0 + bkk) * D_ + n0 + bnn];
        float4 w1 = *(const float4*)&W[(size_t)(k0 + bkk + 16) * D_ + n0 + bnn];
        As[lk + 0][lr] = a0.x; As[lk + 1][lr] = a0.y; As[lk + 2][lr] = a0.z; As[lk + 3][lr] = a0.w;
        As[lk + 4][lr] = a1.x; As[lk + 5][lr] = a1.y; As[lk + 6][lr] = a1.z; As[lk + 7][lr] = a1.w;
        *(float4*)&Bs[bkk][bnn]      = w0;
        *(float4*)&Bs[bkk + 16][bnn] = w1;
        __syncthreads();
#pragma unroll
        for (int k = 0; k < 32; k++) {
            float4 av = *(const float4*)&As[k][4 * ty];
            float4 bv = *(const float4*)&Bs[k][4 * tx];
            ull b01 = pk2(bv.x, bv.y), b23 = pk2(bv.z, bv.w);
            ull aa;
            aa = pk2(av.x, av.x); acc[0][0] = ffma2(aa, b01, acc[0][0]); acc[0][1] = ffma2(aa, b23, acc[0][1]);
            aa = pk2(av.y, av.y); acc[1][0] = ffma2(aa, b01, acc[1][0]); acc[1][1] = ffma2(aa, b23, acc[1][1]);
            aa = pk2(av.z, av.z); acc[2][0] = ffma2(aa, b01, acc[2][0]); acc[2][1] = ffma2(aa, b23, acc[2][1]);
            aa = pk2(av.w, av.w); acc[3][0] = ffma2(aa, b01, acc[3][0]); acc[3][1] = ffma2(aa, b23, acc[3][1]);
        }
        __syncthreads();
    }
    float* crow = out + (size_t)(m0 + 4 * ty) * D_ + n0 + 4 * tx;
#pragma unroll
    for (int i = 0; i < 4; i++) {
        float2 c0 = upk2(acc[i][0]), c1 = upk2(acc[i][1]);
        *(float4*)(crow + (size_t)i * D_) =
            make_float4(tanhf(c0.x), tanhf(c0.y), tanhf(c1.x), tanhf(c1.y));
    }
}

// ---------- launch ----------
extern "C" void kernel_launch(void* const* d_in, const int* in_sizes, int n_in,
                              void* d_out, int out_size) {
    const float* enc  = (const float*)d_in[0];   // (B,S,E)
    const float* dec  = (const float*)d_in[1];   // (B,T,D)
    const void*  mask = d_in[2];                 // (B,S) bool-ish
    const float* Wenc = (const float*)d_in[3];   // (E,D)
    const float* Wfin = (const float*)d_in[4];   // (E+D,D)
    float* out = (float*)d_out;                  // (B,T,D)

    const size_t smem = (size_t)SMEM_FLOATS * sizeof(float);  // 218112 B
    cudaFuncSetAttribute(k_attn, cudaFuncAttributeMaxDynamicSharedMemorySize, (int)smem);

    k_detect<<<1, 256>>>((const unsigned int*)mask);
    k_len<<<B_, 256>>>(mask);

    // context pointer for k_attn output: device global, retrieved via kernel arg trick:
    // k_attn writes g_context directly? It takes ctxout param — pass via symbol-less route:
    k_decproj<<<dim3(E_ / 64, (B_ * T_) / 64), 256>>>(dec, Wenc);

    // We cannot take the address of a __device__ array on the host without
    // cudaGetSymbolAddress (allowed — not an allocation), do it once per call.
    void* ctxptr = nullptr;
    cudaGetSymbolAddress(&ctxptr, g_context);
    k_attn<<<dim3(T_ / 64, B_), 256, smem>>>(enc, (float*)ctxptr);

    k_final<<<dim3(D_ / 64, (B_ * T_) / 64), 256>>>(dec, Wfin, out);
}

// round 11
// speedup vs baseline: 1.0009x; 1.0004x over previous
#include <cuda_runtime.h>
#include <cuda_bf16.h>

#define B_ 16
#define S_ 2048
#define T_ 1024
#define E_ 256
#define D_ 256

typedef unsigned long long ull;

// Scratch (device globals — allocation-free per harness rules)
__device__ float g_dec_proj[B_ * T_ * E_];   // (B,T,E) = dec @ W_enc^T
__device__ float g_context[B_ * T_ * E_];    // (B,T,E)
__device__ int   g_len[B_];
__device__ int   g_kind;                     // 0=int32,1=uint8,2=float32,3=bf16

// ---------- packed f32x2 helpers (2x fp32 throughput on sm_103a) ----------
__device__ __forceinline__ ull pk2(float x, float y) {
    ull r; asm("mov.b64 %0,{%1,%2};" : "=l"(r) : "f"(x), "f"(y)); return r;
}
__device__ __forceinline__ float2 upk2(ull v) {
    float2 r; asm("mov.b64 {%0,%1},%2;" : "=f"(r.x), "=f"(r.y) : "l"(v)); return r;
}
__device__ __forceinline__ ull ffma2(ull a, ull b, ull c) {
    ull d; asm("fma.rn.f32x2 %0,%1,%2,%3;" : "=l"(d) : "l"(a), "l"(b), "l"(c)); return d;
}
__device__ __forceinline__ ull fmul2(ull a, ull b) {
    ull d; asm("mul.rn.f32x2 %0,%1,%2;" : "=l"(d) : "l"(a), "l"(b)); return d;
}

// ---------- mask dtype detection ----------
// Scans only the first 8192 words (32KB) — in-bounds under every candidate dtype.
// Prefix-mask structure guarantees distinguishing word patterns appear.
__global__ void k_detect(const unsigned int* __restrict__ m) {
    __shared__ int fl[3];
    if (threadIdx.x < 3) fl[threadIdx.x] = 0;
    __syncthreads();
    for (int i = threadIdx.x; i < 8192; i += 256) {
        unsigned v = m[i];
        if (v == 0x3F800000u) fl[0] = 1;                                        // float32 1.0
        else if (v == 0x3F803F80u || v == 0x00003F80u) fl[1] = 1;               // bf16 1.0 pair
        else if (v == 0x01010101u || v == 0x00010101u || v == 0x00000101u) fl[2] = 1; // packed bytes
    }
    __syncthreads();
    if (threadIdx.x == 0)
        g_kind = fl[0] ? 2 : (fl[1] ? 3 : (fl[2] ? 1 : 0));
}

// ---------- per-batch valid length (mask is a prefix mask) ----------
__global__ void k_len(const void* __restrict__ m) {
    int b = blockIdx.x;
    int kind = g_kind;
    int c = 0;
    for (int s = threadIdx.x; s < S_; s += 256) {
        int v;
        if (kind == 0)      v = ((const int*)m)[b * S_ + s] != 0;
        else if (kind == 1) v = ((const unsigned char*)m)[b * S_ + s] != 0;
        else if (kind == 2) v = ((const float*)m)[b * S_ + s] != 0.0f;
        else                v = ((const unsigned short*)m)[b * S_ + s] != 0;
        c += v;
    }
    __shared__ int red[256];
    red[threadIdx.x] = c;
    __syncthreads();
    for (int st = 128; st > 0; st >>= 1) {
        if (threadIdx.x < st) red[threadIdx.x] += red[threadIdx.x + st];
        __syncthreads();
    }
    if (threadIdx.x == 0) g_len[b] = red[0];
}

// ---------- K1: dec_proj[m,e] = sum_d dec[m,d] * W_enc[e,d]  (NT GEMM) ----------
__global__ __launch_bounds__(256) void k_decproj(const float* __restrict__ A,
                                                 const float* __restrict__ Bw) {
    __shared__ float As[32][64];   // [k][m] transposed
    __shared__ float Bs[32][64];   // [k][n] transposed
    const int K = D_;
    int m0 = blockIdx.y * 64, n0 = blockIdx.x * 64;
    int tid = threadIdx.x;
    int lr = tid & 63, lk = (tid >> 6) * 8;
    int ty = tid >> 4, tx = tid & 15;
    ull acc[4][2];
#pragma unroll
    for (int i = 0; i < 4; i++) { acc[i][0] = 0ull; acc[i][1] = 0ull; }
    const float* arow = A  + (size_t)(m0 + lr) * K;
    const float* brow = Bw + (size_t)(n0 + lr) * K;
    for (int k0 = 0; k0 < K; k0 += 32) {
        float4 a0 = *(const float4*)(arow + k0 + lk);
        float4 a1 = *(const float4*)(arow + k0 + lk + 4);
        float4 b0 = *(const float4*)(brow + k0 + lk);
        float4 b1 = *(const float4*)(brow + k0 + lk + 4);
        As[lk + 0][lr] = a0.x; As[lk + 1][lr] = a0.y; As[lk + 2][lr] = a0.z; As[lk + 3][lr] = a0.w;
        As[lk + 4][lr] = a1.x; As[lk + 5][lr] = a1.y; As[lk + 6][lr] = a1.z; As[lk + 7][lr] = a1.w;
        Bs[lk + 0][lr] = b0.x; Bs[lk + 1][lr] = b0.y; Bs[lk + 2][lr] = b0.z; Bs[lk + 3][lr] = b0.w;
        Bs[lk + 4][lr] = b1.x; Bs[lk + 5][lr] = b1.y; Bs[lk + 6][lr] = b1.z; Bs[lk + 7][lr] = b1.w;
        __syncthreads();
#pragma unroll
        for (int k = 0; k < 32; k++) {
            float4 av = *(const float4*)&As[k][4 * ty];
            float4 bv = *(const float4*)&Bs[k][4 * tx];
            ull b01 = pk2(bv.x, bv.y), b23 = pk2(bv.z, bv.w);
            ull aa;
            aa = pk2(av.x, av.x); acc[0][0] = ffma2(aa, b01, acc[0][0]); acc[0][1] = ffma2(aa, b23, acc[0][1]);
            aa = pk2(av.y, av.y); acc[1][0] = ffma2(aa, b01, acc[1][0]); acc[1][1] = ffma2(aa, b23, acc[1][1]);
            aa = pk2(av.z, av.z); acc[2][0] = ffma2(aa, b01, acc[2][0]); acc[2][1] = ffma2(aa, b23, acc[2][1]);
            aa = pk2(av.w, av.w); acc[3][0] = ffma2(aa, b01, acc[3][0]); acc[3][1] = ffma2(aa, b23, acc[3][1]);
        }
        __syncthreads();
    }
    float* crow = g_dec_proj + (size_t)(m0 + 4 * ty) * E_ + n0 + 4 * tx;
#pragma unroll
    for (int i = 0; i < 4; i++) {
        float2 c0 = upk2(acc[i][0]), c1 = upk2(acc[i][1]);
        *(float4*)(crow + (size_t)i * E_) = make_float4(c0.x, c0.y, c1.x, c1.y);
    }
}

// ---------- K2: fused flash attention (K == V == enc_states) ----------
// Grid: (T/64, B). One CTA = 64 dec rows. Loops only over valid-prefix chunks.
#define SMEM_FLOATS (256 * 64 + 256 * 68 + 64 * 256 + 64 * 68)

__global__ __launch_bounds__(256, 1) void k_attn(const float* __restrict__ enc,
                                                 float* __restrict__ ctxout) {
    extern __shared__ float sm[];
    float* Qs = sm;                 // [256][64]  (k-major transposed dec_proj tile)
    float* Es = Qs + 256 * 64;      // [256][68]  (k-major transposed enc chunk, padded)
    float* Vs = Es + 256 * 68;      // [64][256]  (natural enc chunk, XOR-swizzled)
    float* Ps = Vs + 64 * 256;      // [64][68]   (softmax weights)

    int b = blockIdx.y;
    int t0 = blockIdx.x * 64;
    int tid = threadIdx.x, ty = tid >> 4, tx = tid & 15;
    int lr = tid & 63, le8 = (tid >> 6) * 8;

    // Load Q tile transposed: Qs[e][t_local]
    const float* qrow = g_dec_proj + ((size_t)b * T_ + t0 + lr) * E_;
#pragma unroll
    for (int e = le8; e < 256; e += 32) {
        float4 v0 = *(const float4*)(qrow + e);
        float4 v1 = *(const float4*)(qrow + e + 4);
        Qs[(e + 0) * 64 + lr] = v0.x; Qs[(e + 1) * 64 + lr] = v0.y;
        Qs[(e + 2) * 64 + lr] = v0.z; Qs[(e + 3) * 64 + lr] = v0.w;
        Qs[(e + 4) * 64 + lr] = v1.x; Qs[(e + 5) * 64 + lr] = v1.y;
        Qs[(e + 6) * 64 + lr] = v1.z; Qs[(e + 7) * 64 + lr] = v1.w;
    }

    int len = g_len[b];
    int nch = (len + 63) >> 6;

    float mr[4], lrw[4];
    ull acc[4][8];
#pragma unroll
    for (int i = 0; i < 4; i++) {
        mr[i] = __int_as_float(0xff800000); lrw[i] = 0.0f;
#pragma unroll
        for (int j = 0; j < 8; j++) acc[i][j] = 0ull;
    }

    int vsw = (lr & 7) * 4;  // Vs write swizzle (low-bank XOR, keeps 16B alignment)

    for (int sc = 0; sc < nch; sc++) {
        int s0 = sc << 6;
        const float* erow = enc + ((size_t)b * S_ + s0 + lr) * E_;
#pragma unroll
        for (int e = le8; e < 256; e += 32) {
            float4 v0 = *(const float4*)(erow + e);
            float4 v1 = *(const float4*)(erow + e + 4);
            *(float4*)&Vs[lr * 256 + ((e) ^ vsw)]     = v0;
            *(float4*)&Vs[lr * 256 + ((e + 4) ^ vsw)] = v1;
            Es[(e + 0) * 68 + lr] = v0.x; Es[(e + 1) * 68 + lr] = v0.y;
            Es[(e + 2) * 68 + lr] = v0.z; Es[(e + 3) * 68 + lr] = v0.w;
            Es[(e + 4) * 68 + lr] = v1.x; Es[(e + 5) * 68 + lr] = v1.y;
            Es[(e + 6) * 68 + lr] = v1.z; Es[(e + 7) * 68 + lr] = v1.w;
        }
        __syncthreads();

        // -------- Phase A: scores tile (64x64) = Q @ enc^T --------
        ull s2[4][2];
#pragma unroll
        for (int i = 0; i < 4; i++) { s2[i][0] = 0ull; s2[i][1] = 0ull; }
#pragma unroll 8
        for (int k = 0; k < 256; k++) {
            float4 q  = *(const float4*)&Qs[k * 64 + 4 * ty];
            float4 e4 = *(const float4*)&Es[k * 68 + 4 * tx];
            ull b01 = pk2(e4.x, e4.y), b23 = pk2(e4.z, e4.w);
            ull aa;
            aa = pk2(q.x, q.x); s2[0][0] = ffma2(aa, b01, s2[0][0]); s2[0][1] = ffma2(aa, b23, s2[0][1]);
            aa = pk2(q.y, q.y); s2[1][0] = ffma2(aa, b01, s2[1][0]); s2[1][1] = ffma2(aa, b23, s2[1][1]);
            aa = pk2(q.z, q.z); s2[2][0] = ffma2(aa, b01, s2[2][0]); s2[2][1] = ffma2(aa, b23, s2[2][1]);
            aa = pk2(q.w, q.w); s2[3][0] = ffma2(aa, b01, s2[3][0]); s2[3][1] = ffma2(aa, b23, s2[3][1]);
        }

        // -------- online softmax update --------
        int rem = len - s0;
#pragma unroll
        for (int i = 0; i < 4; i++) {
            float2 c0 = upk2(s2[i][0]), c1 = upk2(s2[i][1]);
            float sv0 = c0.x, sv1 = c0.y, sv2 = c1.x, sv3 = c1.y;
            if (rem < 64) {
                const float NINF = __int_as_float(0xff800000);
                if (4 * tx + 0 >= rem) sv0 = NINF;
                if (4 * tx + 1 >= rem) sv1 = NINF;
                if (4 * tx + 2 >= rem) sv2 = NINF;
                if (4 * tx + 3 >= rem) sv3 = NINF;
            }
            float cm = fmaxf(fmaxf(sv0, sv1), fmaxf(sv2, sv3));
#pragma unroll
            for (int off = 1; off < 16; off <<= 1)
                cm = fmaxf(cm, __shfl_xor_sync(0xffffffffu, cm, off));
            float nm = fmaxf(mr[i], cm);
            float scale = __expf(mr[i] - nm);
            mr[i] = nm;
            float p0 = __expf(sv0 - nm), p1 = __expf(sv1 - nm);
            float p2 = __expf(sv2 - nm), p3 = __expf(sv3 - nm);
            float rs = (p0 + p1) + (p2 + p3);
#pragma unroll
            for (int off = 1; off < 16; off <<= 1)
                rs += __shfl_xor_sync(0xffffffffu, rs, off);
            lrw[i] = lrw[i] * scale + rs;
            ull sc2 = pk2(scale, scale);
#pragma unroll
            for (int j = 0; j < 8; j++) acc[i][j] = fmul2(sc2, acc[i][j]);
            *(float4*)&Ps[(4 * ty + i) * 68 + 4 * tx] = make_float4(p0, p1, p2, p3);
        }
        __syncthreads();

        // -------- Phase B: context += P @ V --------
#pragma unroll 1
        for (int s4 = 0; s4 < 64; s4 += 4) {
            float4 pr0 = *(const float4*)&Ps[(4 * ty + 0) * 68 + s4];
            float4 pr1 = *(const float4*)&Ps[(4 * ty + 1) * 68 + s4];
            float4 pr2 = *(const float4*)&Ps[(4 * ty + 2) * 68 + s4];
            float4 pr3 = *(const float4*)&Ps[(4 * ty + 3) * 68 + s4];
            float pm0[4] = {pr0.x, pr0.y, pr0.z, pr0.w};
            float pm1[4] = {pr1.x, pr1.y, pr1.z, pr1.w};
            float pm2[4] = {pr2.x, pr2.y, pr2.z, pr2.w};
            float pm3[4] = {pr3.x, pr3.y, pr3.z, pr3.w};
#pragma unroll
            for (int u = 0; u < 4; u++) {
                const float* vb = &Vs[(s4 + u) * 256];
                int co = (2 * tx) ^ (((s4 + u) & 7) * 4);
                ull pp0 = pk2(pm0[u], pm0[u]);
                ull pp1 = pk2(pm1[u], pm1[u]);
                ull pp2 = pk2(pm2[u], pm2[u]);
                ull pp3 = pk2(pm3[u], pm3[u]);
#pragma unroll
                for (int jj = 0; jj < 8; jj++) {
                    ull v2 = *(const ull*)(vb + co + 32 * jj);
                    acc[0][jj] = ffma2(pp0, v2, acc[0][jj]);
                    acc[1][jj] = ffma2(pp1, v2, acc[1][jj]);
                    acc[2][jj] = ffma2(pp2, v2, acc[2][jj]);
                    acc[3][jj] = ffma2(pp3, v2, acc[3][jj]);
                }
            }
        }
        __syncthreads();
    }

    // -------- epilogue: normalize and write context --------
#pragma unroll
    for (int i = 0; i < 4; i++) {
        float inv = 1.0f / lrw[i];
        float* orow = ctxout + ((size_t)b * T_ + t0 + 4 * ty + i) * E_ + 2 * tx;
#pragma unroll
        for (int jj = 0; jj < 8; jj++) {
            float2 c = upk2(acc[i][jj]);
            *(float2*)(orow + 32 * jj) = make_float2(c.x * inv, c.y * inv);
        }
    }
}

// ---------- K3: out = tanh([context, dec] @ W_fin)  (NN GEMM, K=512) ----------
__global__ __launch_bounds__(256) void k_final(const float* __restrict__ dec,
                                               const float* __restrict__ W,
                                               float* __restrict__ out) {
    __shared__ float As[32][64];   // [k][m] transposed
    __shared__ float Bs[32][68];   // [k][n] natural, padded
    int m0 = blockIdx.y * 64, n0 = blockIdx.x * 64;
    int tid = threadIdx.x;
    int lr = tid & 63, lk = (tid >> 6) * 8;
    int ty = tid >> 4, tx = tid & 15;
    int bkk = tid >> 4, bnn = (tid & 15) * 4;
    ull acc[4][2];
#pragma unroll
    for (int i = 0; i < 4; i++) { acc[i][0] = 0ull; acc[i][1] = 0ull; }

    for (int k0 = 0; k0 < 512; k0 += 32) {
        const float* arow = (k0 < 256)
            ? (g_context + (size_t)(m0 + lr) * E_ + k0)
            : (dec + (size_t)(m0 + lr) * D_ + (k0 - 256));
        float4 a0 = *(const float4*)(arow + lk);
        float4 a1 = *(const float4*)(arow + lk + 4);
        float4 w0 = *(const float4*)&W[(size_t)(k0 + bkk) * D_ + n0 + bnn];
        float4 w1 = *(const float4*)&W[(size_t)(k0 + bkk + 16) * D_ + n0 + bnn];
        As[lk + 0][lr] = a0.x; As[lk + 1][lr] = a0.y; As[lk + 2][lr] = a0.z; As[lk + 3][lr] = a0.w;
        As[lk + 4][lr] = a1.x; As[lk + 5][lr] = a1.y; As[lk + 6][lr] = a1.z; As[lk + 7][lr] = a1.w;
        *(float4*)&Bs[bkk][bnn]      = w0;
        *(float4*)&Bs[bkk + 16][bnn] = w1;
        __syncthreads();
#pragma unroll
        for (int k = 0; k < 32; k++) {
            float4 av = *(const float4*)&As[k][4 * ty];
            float4 bv = *(const float4*)&Bs[k][4 * tx];
            ull b01 = pk2(bv.x, bv.y), b23 = pk2(bv.z, bv.w);
            ull aa;
            aa = pk2(av.x, av.x); acc[0][0] = ffma2(aa, b01, acc[0][0]); acc[0][1] = ffma2(aa, b23, acc[0][1]);
            aa = pk2(av.y, av.y); acc[1][0] = ffma2(aa, b01, acc[1][0]); acc[1][1] = ffma2(aa, b23, acc[1][1]);
            aa = pk2(av.z, av.z); acc[2][0] = ffma2(aa, b01, acc[2][0]); acc[2][1] = ffma2(aa, b23, acc[2][1]);
            aa = pk2(av.w, av.w); acc[3][0] = ffma2(aa, b01, acc[3][0]); acc[3][1] = ffma2(aa, b23, acc[3][1]);
        }
        __syncthreads();
    }
    float* crow = out + (size_t)(m0 + 4 * ty) * D_ + n0 + 4 * tx;
#pragma unroll
    for (int i = 0; i < 4; i++) {
        float2 c0 = upk2(acc[i][0]), c1 = upk2(acc[i][1]);
        *(float4*)(crow + (size_t)i * D_) =
            make_float4(tanhf(c0.x), tanhf(c0.y), tanhf(c1.x), tanhf(c1.y));
    }
}

// ---------- launch ----------
extern "C" void kernel_launch(void* const* d_in, const int* in_sizes, int n_in,
                              void* d_out, int out_size) {
    const float* enc  = (const float*)d_in[0];   // (B,S,E)
    const float* dec  = (const float*)d_in[1];   // (B,T,D)
    const void*  mask = d_in[2];                 // (B,S) bool-ish
    const float* Wenc = (const float*)d_in[3];   // (E,D)
    const float* Wfin = (const float*)d_in[4];   // (E+D,D)
    float* out = (float*)d_out;                  // (B,T,D)

    const size_t smem = (size_t)SMEM_FLOATS * sizeof(float);  // 218112 B
    cudaFuncSetAttribute(k_attn, cudaFuncAttributeMaxDynamicSharedMemorySize, (int)smem);

    k_detect<<<1, 256>>>((const unsigned int*)mask);
    k_len<<<B_, 256>>>(mask);

    // context pointer for k_attn output: device global, retrieved via kernel arg trick:
    // k_attn writes g_context directly? It takes ctxout param — pass via symbol-less route:
    k_decproj<<<dim3(E_ / 64, (B_ * T_) / 64), 256>>>(dec, Wenc);

    // We cannot take the address of a __device__ array on the host without
    // cudaGetSymbolAddress (allowed — not an allocation), do it once per call.
    void* ctxptr = nullptr;
    cudaGetSymbolAddress(&ctxptr, g_context);
    k_attn<<<dim3(T_ / 64, B_), 256, smem>>>(enc, (float*)ctxptr);

    k_final<<<dim3(D_ / 64, (B_ * T_) / 64), 256>>>(dec, Wfin, out);
}